// round 6
// baseline (speedup 1.0000x reference)
#include <cuda_runtime.h>
#include <cuda_bf16.h>
#include <math.h>
#include <stdint.h>

#define NHEADS  16
#define HDIM    64
#define BATCH   2
#define SEQ     2048
#define DMODEL  1024
#define MROWS   (BATCH*SEQ)   // 4096

// ---------------------------------------------------------------------------
// Scratch (device globals — no allocation allowed)
// ---------------------------------------------------------------------------
__device__ float g_Q[MROWS*DMODEL];
__device__ float g_K[MROWS*DMODEL];
__device__ float g_V[MROWS*DMODEL];

__device__ __nv_bfloat16 g_xh[MROWS*DMODEL];
__device__ __nv_bfloat16 g_xl[MROWS*DMODEL];
__device__ __nv_bfloat16 g_oh[MROWS*DMODEL];
__device__ __nv_bfloat16 g_ol[MROWS*DMODEL];
__device__ __nv_bfloat16 g_Wqh[DMODEL*DMODEL];
__device__ __nv_bfloat16 g_Wql[DMODEL*DMODEL];
__device__ __nv_bfloat16 g_Wkh[DMODEL*DMODEL];
__device__ __nv_bfloat16 g_Wkl[DMODEL*DMODEL];
__device__ __nv_bfloat16 g_Wvh[DMODEL*DMODEL];
__device__ __nv_bfloat16 g_Wvl[DMODEL*DMODEL];
__device__ __nv_bfloat16 g_Woh[DMODEL*DMODEL];
__device__ __nv_bfloat16 g_Wol[DMODEL*DMODEL];

// attention operands (bf16 hi/lo)
__device__ __nv_bfloat16 g_Qh[MROWS*DMODEL];
__device__ __nv_bfloat16 g_Ql[MROWS*DMODEL];
__device__ __nv_bfloat16 g_Kh[MROWS*DMODEL];
__device__ __nv_bfloat16 g_Kl[MROWS*DMODEL];
__device__ __nv_bfloat16 g_Vth[DMODEL*MROWS];   // V^T: [1024][4096]
__device__ __nv_bfloat16 g_Vtl[DMODEL*MROWS];

// ---------------------------------------------------------------------------
// PTX helpers (sm_80-class only — tcgen05 NOT available on this target)
// ---------------------------------------------------------------------------
__device__ __forceinline__ uint32_t smem_u32(const void* p) {
    uint32_t a;
    asm("{ .reg .u64 t; cvta.to.shared.u64 t, %1; cvt.u32.u64 %0, t; }"
        : "=r"(a) : "l"(p));
    return a;
}

__device__ __forceinline__ void cp_async16(uint32_t dst, const void* src) {
    asm volatile("cp.async.cg.shared.global [%0], [%1], 16;" :: "r"(dst), "l"(src));
}
__device__ __forceinline__ void cp_commit() { asm volatile("cp.async.commit_group;"); }

__device__ __forceinline__ void ldm_x4(uint32_t addr, uint32_t& r0, uint32_t& r1,
                                       uint32_t& r2, uint32_t& r3) {
    asm volatile("ldmatrix.sync.aligned.m8n8.x4.shared.b16 {%0,%1,%2,%3}, [%4];"
                 : "=r"(r0), "=r"(r1), "=r"(r2), "=r"(r3) : "r"(addr));
}
__device__ __forceinline__ void ldm_x2(uint32_t addr, uint32_t& r0, uint32_t& r1) {
    asm volatile("ldmatrix.sync.aligned.m8n8.x2.shared.b16 {%0,%1}, [%2];"
                 : "=r"(r0), "=r"(r1) : "r"(addr));
}

__device__ __forceinline__ void mma_bf16(float* d, const uint32_t* a, const uint32_t* b) {
    asm volatile(
        "mma.sync.aligned.m16n8k16.row.col.f32.bf16.bf16.f32 "
        "{%0,%1,%2,%3}, {%4,%5,%6,%7}, {%8,%9}, {%0,%1,%2,%3};"
        : "+f"(d[0]), "+f"(d[1]), "+f"(d[2]), "+f"(d[3])
        : "r"(a[0]), "r"(a[1]), "r"(a[2]), "r"(a[3]), "r"(b[0]), "r"(b[1]));
}

// 128B-row swizzle (8 chunks of 16B), chunk ^= row&7
__device__ __forceinline__ uint32_t sw_off(int row, int chunk) {
    return (uint32_t)(row * 128 + ((chunk ^ (row & 7)) << 4));
}
// 256B-row swizzle (16 chunks of 16B), low-3 bits of chunk ^= row&7
__device__ __forceinline__ uint32_t swv_off(int row, int chunk) {
    return (uint32_t)(row * 256 + ((chunk ^ (row & 7)) << 4));
}

// fast angular weight: w = max(1 - acos(clip(c))/pi, eps)^16
// acos via A&S 4.4.46: acos(t) = sqrt(1-t)*P7(t), |err| ~ 2e-8 rad
__device__ __forceinline__ float ang_w(float x) {
    float c = fminf(fmaxf(x, -0.999f), 0.999f);
    float t = fabsf(c);
    float p = -0.0012624911f;
    p = fmaf(p, t,  0.0066700901f);
    p = fmaf(p, t, -0.0170881256f);
    p = fmaf(p, t,  0.0308918810f);
    p = fmaf(p, t, -0.0501743046f);
    p = fmaf(p, t,  0.0889789874f);
    p = fmaf(p, t, -0.2145988016f);
    p = fmaf(p, t,  1.5707963050f);
    float u = 1.0f - t;                 // >= 0.001
    float r = u * __frsqrt_rn(u) * p * 0.31830988618379067f;   // acos(|c|)/pi
    float s = (c >= 0.0f) ? (1.0f - r) : r;
    s = fmaxf(s, 1e-6f);
    float s2 = s*s, s4 = s2*s2, s8 = s4*s4;
    return s8 * s8;
}

// ---------------------------------------------------------------------------
// Split fp32 -> bf16 hi + bf16 lo (residual)
// ---------------------------------------------------------------------------
__global__ void split_kernel(const float* __restrict__ s,
                             __nv_bfloat16* __restrict__ h,
                             __nv_bfloat16* __restrict__ l, int n4)
{
    int i = blockIdx.x * blockDim.x + threadIdx.x;
    if (i >= n4) return;
    float4 v = reinterpret_cast<const float4*>(s)[i];
    __nv_bfloat16 h0 = __float2bfloat16(v.x);
    __nv_bfloat16 h1 = __float2bfloat16(v.y);
    __nv_bfloat16 h2 = __float2bfloat16(v.z);
    __nv_bfloat16 h3 = __float2bfloat16(v.w);
    __nv_bfloat16 l0 = __float2bfloat16(v.x - __bfloat162float(h0));
    __nv_bfloat16 l1 = __float2bfloat16(v.y - __bfloat162float(h1));
    __nv_bfloat16 l2 = __float2bfloat16(v.z - __bfloat162float(h2));
    __nv_bfloat16 l3 = __float2bfloat16(v.w - __bfloat162float(h3));
    __nv_bfloat162* hp = reinterpret_cast<__nv_bfloat162*>(h);
    __nv_bfloat162* lp = reinterpret_cast<__nv_bfloat162*>(l);
    hp[2*i]   = __nv_bfloat162(h0, h1);
    hp[2*i+1] = __nv_bfloat162(h2, h3);
    lp[2*i]   = __nv_bfloat162(l0, l1);
    lp[2*i+1] = __nv_bfloat162(l2, l3);
}

// ---------------------------------------------------------------------------
// mma.sync bf16 GEMM core (NT): C = A*B^T (+bias), hi/lo split, 3-stage pipe.
// Tile 128x128, KC=64, 256 threads, 8 warps (2Mx4N).
// ---------------------------------------------------------------------------
#define G_SUB      16384
#define G_STAGE_B  (4*G_SUB)                // 64 KB
#define G_NSTAGE   3
#define G_SMEM_BYTES (G_NSTAGE*G_STAGE_B)   // 196608

__device__ __forceinline__ void gemm_core(
    const __nv_bfloat16* __restrict__ Ah, const __nv_bfloat16* __restrict__ Al,
    const __nv_bfloat16* __restrict__ Bh, const __nv_bfloat16* __restrict__ Bl,
    const float* __restrict__ bias, float* __restrict__ C,
    int N, int K, uint32_t sb)
{
    const int tid  = threadIdx.x;
    const int wid  = tid >> 5, lane = tid & 31;
    const int wm   = wid & 1;
    const int wn   = wid >> 1;
    const int bn = blockIdx.x * 128, bm = blockIdx.y * 128;

    const __nv_bfloat16* gsrc[4] = {Ah, Al, Bh, Bl};
    const int rbase[4] = {bm, bm, bn, bn};

    float acc[4][4][4];
    #pragma unroll
    for (int i = 0; i < 4; i++)
        #pragma unroll
        for (int j = 0; j < 4; j++)
            #pragma unroll
            for (int r = 0; r < 4; r++) acc[i][j][r] = 0.0f;

    const int nk = K / 64;

    auto load_stage = [&](int c) {
        uint32_t st = sb + (uint32_t)(c % G_NSTAGE) * G_STAGE_B;
        size_t koff = (size_t)c * 64;
        #pragma unroll
        for (int t = 0; t < 4; t++) {
            const __nv_bfloat16* g = gsrc[t];
            #pragma unroll
            for (int u = 0; u < 4; u++) {
                int idx = tid + u * 256;
                int r = idx >> 3, ch = idx & 7;
                const void* src = g + (size_t)(rbase[t] + r) * K + koff + ch * 8;
                cp_async16(st + t * G_SUB + sw_off(r, ch), src);
            }
        }
    };

    load_stage(0); cp_commit();
    load_stage(1); cp_commit();

    for (int c = 0; c < nk; c++) {
        asm volatile("cp.async.wait_group 1;" ::: "memory");
        __syncthreads();

        uint32_t st  = sb + (uint32_t)(c % G_NSTAGE) * G_STAGE_B;
        uint32_t ahB = st, alB = st + G_SUB, bhB = st + 2*G_SUB, blB = st + 3*G_SUB;

        #pragma unroll
        for (int ks = 0; ks < 4; ks++) {
            uint32_t bh[4][2], bl[4][2];
            {
                int r  = wn * 32 + (lane & 7);
                int chv = ks * 2 + ((lane >> 3) & 1);
                #pragma unroll
                for (int nf = 0; nf < 4; nf++) {
                    int row = r + nf * 8;
                    uint32_t off = sw_off(row, chv);
                    ldm_x2(bhB + off, bh[nf][0], bh[nf][1]);
                    ldm_x2(blB + off, bl[nf][0], bl[nf][1]);
                }
            }
            #pragma unroll
            for (int mf = 0; mf < 4; mf++) {
                int row = wm * 64 + mf * 16 + (lane & 15);
                int chv = ks * 2 + (lane >> 4);
                uint32_t off = sw_off(row, chv);
                uint32_t ah[4], al[4];
                ldm_x4(ahB + off, ah[0], ah[1], ah[2], ah[3]);
                ldm_x4(alB + off, al[0], al[1], al[2], al[3]);
                #pragma unroll
                for (int nf = 0; nf < 4; nf++) {
                    mma_bf16(acc[mf][nf], ah, bh[nf]);
                    mma_bf16(acc[mf][nf], ah, bl[nf]);
                    mma_bf16(acc[mf][nf], al, bh[nf]);
                }
            }
        }
        __syncthreads();
        if (c + 2 < nk) load_stage(c + 2);
        cp_commit();
    }

    const int g  = lane >> 2;
    const int tq = lane & 3;
    #pragma unroll
    for (int mf = 0; mf < 4; mf++) {
        int row0 = bm + wm * 64 + mf * 16 + g;
        #pragma unroll
        for (int nf = 0; nf < 4; nf++) {
            int col = bn + wn * 32 + nf * 8 + 2 * tq;
            float b0 = 0.f, b1 = 0.f;
            if (bias) { b0 = bias[col]; b1 = bias[col + 1]; }
            float2 v0, v1;
            v0.x = acc[mf][nf][0] + b0; v0.y = acc[mf][nf][1] + b1;
            v1.x = acc[mf][nf][2] + b0; v1.y = acc[mf][nf][3] + b1;
            *reinterpret_cast<float2*>(C + (size_t)row0 * N + col)       = v0;
            *reinterpret_cast<float2*>(C + (size_t)(row0 + 8) * N + col) = v1;
        }
    }
}

// merged QKV projection: grid.z selects weight/output
__global__ __launch_bounds__(256) void gemm_qkv_kernel()
{
    extern __shared__ __align__(128) char smem[];
    uint32_t sb = smem_u32(smem);
    const __nv_bfloat16* Bh;
    const __nv_bfloat16* Bl;
    float* C;
    switch (blockIdx.z) {
        case 0:  Bh = g_Wqh; Bl = g_Wql; C = g_Q; break;
        case 1:  Bh = g_Wkh; Bl = g_Wkl; C = g_K; break;
        default: Bh = g_Wvh; Bl = g_Wvl; C = g_V; break;
    }
    gemm_core(g_xh, g_xl, Bh, Bl, nullptr, C, DMODEL, DMODEL, sb);
}

// single GEMM (output projection, with bias)
__global__ __launch_bounds__(256) void gemm_tc(
    const __nv_bfloat16* __restrict__ Ah, const __nv_bfloat16* __restrict__ Al,
    const __nv_bfloat16* __restrict__ Bh, const __nv_bfloat16* __restrict__ Bl,
    const float* __restrict__ bias, float* __restrict__ C, int N, int K)
{
    extern __shared__ __align__(128) char smem[];
    uint32_t sb = smem_u32(smem);
    gemm_core(Ah, Al, Bh, Bl, bias, C, N, K, sb);
}

// ---------------------------------------------------------------------------
// L2-normalize each 64-float head chunk of g_Q / g_K, write bf16 hi/lo.
// ---------------------------------------------------------------------------
__global__ void l2norm_split_kernel()
{
    const int NC = MROWS * NHEADS;
    int gw   = (blockIdx.x * blockDim.x + threadIdx.x) >> 5;
    int lane = threadIdx.x & 31;
    const float* src;
    __nv_bfloat16 *dh, *dl;
    size_t off;
    if (gw < NC) { src = g_Q; dh = g_Qh; dl = g_Ql; off = (size_t)gw * HDIM; }
    else         { src = g_K; dh = g_Kh; dl = g_Kl; off = (size_t)(gw - NC) * HDIM; }
    float v0 = src[off + lane];
    float v1 = src[off + lane + 32];
    float ss = v0*v0 + v1*v1;
    #pragma unroll
    for (int o = 16; o > 0; o >>= 1) ss += __shfl_xor_sync(0xffffffffu, ss, o);
    float inv = 1.0f / fmaxf(sqrtf(ss), 1e-6f);
    float n0 = v0 * inv, n1 = v1 * inv;
    __nv_bfloat16 h0 = __float2bfloat16(n0);
    __nv_bfloat16 h1 = __float2bfloat16(n1);
    dh[off + lane]      = h0;
    dh[off + lane + 32] = h1;
    dl[off + lane]      = __float2bfloat16(n0 - __bfloat162float(h0));
    dl[off + lane + 32] = __float2bfloat16(n1 - __bfloat162float(h1));
}

// ---------------------------------------------------------------------------
// V transpose + split: g_V [4096][1024] fp32 -> g_Vth/g_Vtl [1024][4096] bf16
// ---------------------------------------------------------------------------
__global__ void vtrans_split_kernel()
{
    __shared__ float t[32][33];
    int s0 = blockIdx.x * 32, d0 = blockIdx.y * 32;
    int x = threadIdx.x, y = threadIdx.y;
    #pragma unroll
    for (int k = 0; k < 4; k++)
        t[y + k*8][x] = g_V[(size_t)(s0 + y + k*8) * DMODEL + d0 + x];
    __syncthreads();
    #pragma unroll
    for (int k = 0; k < 4; k++) {
        int d = d0 + y + k*8;
        float v = t[x][y + k*8];
        __nv_bfloat16 h = __float2bfloat16(v);
        g_Vth[(size_t)d * MROWS + s0 + x] = h;
        g_Vtl[(size_t)d * MROWS + s0 + x] = __float2bfloat16(v - __bfloat162float(h));
    }
}

// ---------------------------------------------------------------------------
// mma.sync angular attention (2-stage, proven) + fast acos polynomial.
// grid (16 q-tiles, 32 bh), 256 threads, 8 warps = 4 (q) x 2 (k-half).
// ---------------------------------------------------------------------------
#define A_Q     0
#define A_STG   32768
#define A_STAGE 65536
#define A_SMEM  (A_STG + 2*A_STAGE)    // 163840

__global__ __launch_bounds__(256, 1) void attn_mma_kernel()
{
    extern __shared__ __align__(128) char smem[];
    uint32_t sb = smem_u32(smem);
    const int tid  = threadIdx.x;
    const int wid  = tid >> 5, lane = tid & 31;
    const int wq   = wid & 3;
    const int wn   = wid >> 2;
    const int qt   = blockIdx.x;
    const int b    = blockIdx.y / NHEADS;
    const int h    = blockIdx.y % NHEADS;
    const int m0   = b * SEQ + qt * 128;
    const int cb   = h * HDIM;

    #pragma unroll
    for (int u = 0; u < 4; u++) {
        int idx = tid + u * 256;
        int r = idx >> 3, ch = idx & 7;
        const __nv_bfloat16* s0 = g_Qh + (size_t)(m0 + r) * DMODEL + cb + ch * 8;
        const __nv_bfloat16* s1 = g_Ql + (size_t)(m0 + r) * DMODEL + cb + ch * 8;
        cp_async16(sb + A_Q + sw_off(r, ch), s0);
        cp_async16(sb + A_Q + 16384 + sw_off(r, ch), s1);
    }

    auto load_stage = [&](int kt) {
        uint32_t st = sb + A_STG + (uint32_t)(kt & 1) * A_STAGE;
        int k0 = b * SEQ + kt * 128;
        #pragma unroll
        for (int u = 0; u < 4; u++) {
            int idx = tid + u * 256;
            int r = idx >> 3, ch = idx & 7;
            cp_async16(st + sw_off(r, ch),
                       g_Kh + (size_t)(k0 + r) * DMODEL + cb + ch * 8);
            cp_async16(st + 16384 + sw_off(r, ch),
                       g_Kl + (size_t)(k0 + r) * DMODEL + cb + ch * 8);
        }
        #pragma unroll
        for (int u = 0; u < 4; u++) {
            int idx = tid + u * 256;
            int r = idx >> 4, ch = idx & 15;
            cp_async16(st + 32768 + swv_off(r, ch),
                       g_Vth + (size_t)(cb + r) * MROWS + k0 + ch * 8);
            cp_async16(st + 49152 + swv_off(r, ch),
                       g_Vtl + (size_t)(cb + r) * MROWS + k0 + ch * 8);
        }
    };

    load_stage(0);
    cp_commit();

    float oacc[2][8][4];
    #pragma unroll
    for (int mf = 0; mf < 2; mf++)
        #pragma unroll
        for (int nf = 0; nf < 8; nf++)
            #pragma unroll
            for (int r = 0; r < 4; r++) oacc[mf][nf][r] = 0.0f;
    float rsum[2][2] = {{0.f,0.f},{0.f,0.f}};

    for (int kt = 0; kt < 16; kt++) {
        if (kt + 1 < 16) { load_stage(kt + 1); cp_commit();
                           asm volatile("cp.async.wait_group 1;" ::: "memory"); }
        else             { asm volatile("cp.async.wait_group 0;" ::: "memory"); }
        __syncthreads();

        uint32_t st  = sb + A_STG + (uint32_t)(kt & 1) * A_STAGE;
        uint32_t khB = st, klB = st + 16384, vhB = st + 32768, vlB = st + 49152;

        float sacc[2][8][4];
        #pragma unroll
        for (int mf = 0; mf < 2; mf++)
            #pragma unroll
            for (int nf = 0; nf < 8; nf++)
                #pragma unroll
                for (int r = 0; r < 4; r++) sacc[mf][nf][r] = 0.0f;

        #pragma unroll
        for (int ks = 0; ks < 4; ks++) {
            uint32_t kh[8][2], kl[8][2];
            {
                int r  = wn * 64 + (lane & 7);
                int chv = ks * 2 + ((lane >> 3) & 1);
                #pragma unroll
                for (int nf = 0; nf < 8; nf++) {
                    uint32_t off = sw_off(r + nf * 8, chv);
                    ldm_x2(khB + off, kh[nf][0], kh[nf][1]);
                    ldm_x2(klB + off, kl[nf][0], kl[nf][1]);
                }
            }
            #pragma unroll
            for (int mf = 0; mf < 2; mf++) {
                int row = wq * 32 + mf * 16 + (lane & 15);
                int chv = ks * 2 + (lane >> 4);
                uint32_t off = sw_off(row, chv);
                uint32_t qh[4], ql[4];
                ldm_x4(sb + A_Q + off, qh[0], qh[1], qh[2], qh[3]);
                ldm_x4(sb + A_Q + 16384 + off, ql[0], ql[1], ql[2], ql[3]);
                #pragma unroll
                for (int nf = 0; nf < 8; nf++) {
                    mma_bf16(sacc[mf][nf], qh, kh[nf]);
                    mma_bf16(sacc[mf][nf], qh, kl[nf]);
                    mma_bf16(sacc[mf][nf], ql, kh[nf]);
                }
            }
        }

        #pragma unroll
        for (int j = 0; j < 4; j++) {
            uint32_t wh[2][4], wl[2][4];
            #pragma unroll
            for (int mf = 0; mf < 2; mf++) {
                #pragma unroll
                for (int half = 0; half < 2; half++) {
                    int nf = 2*j + half;
                    float w[4];
                    #pragma unroll
                    for (int e = 0; e < 4; e++) w[e] = ang_w(sacc[mf][nf][e]);
                    rsum[mf][0] += w[0] + w[1];
                    rsum[mf][1] += w[2] + w[3];
                    __nv_bfloat162 ph0 = __floats2bfloat162_rn(w[0], w[1]);
                    __nv_bfloat162 ph1 = __floats2bfloat162_rn(w[2], w[3]);
                    float r0 = w[0] - __bfloat162float(ph0.x);
                    float r1 = w[1] - __bfloat162float(ph0.y);
                    float r2 = w[2] - __bfloat162float(ph1.x);
                    float r3 = w[3] - __bfloat162float(ph1.y);
                    __nv_bfloat162 pl0 = __floats2bfloat162_rn(r0, r1);
                    __nv_bfloat162 pl1 = __floats2bfloat162_rn(r2, r3);
                    wh[mf][0 + half*2] = *reinterpret_cast<uint32_t*>(&ph0);
                    wh[mf][1 + half*2] = *reinterpret_cast<uint32_t*>(&ph1);
                    wl[mf][0 + half*2] = *reinterpret_cast<uint32_t*>(&pl0);
                    wl[mf][1 + half*2] = *reinterpret_cast<uint32_t*>(&pl1);
                }
            }
            uint32_t vh[8][2], vl[8][2];
            {
                int r   = lane & 7;
                int chv = wn * 8 + j * 2 + ((lane >> 3) & 1);
                #pragma unroll
                for (int nf = 0; nf < 8; nf++) {
                    uint32_t off = swv_off(r + nf * 8, chv);
                    ldm_x2(vhB + off, vh[nf][0], vh[nf][1]);
                    ldm_x2(vlB + off, vl[nf][0], vl[nf][1]);
                }
            }
            #pragma unroll
            for (int mf = 0; mf < 2; mf++)
                #pragma unroll
                for (int nf = 0; nf < 8; nf++) {
                    mma_bf16(oacc[mf][nf], wh[mf], vh[nf]);
                    mma_bf16(oacc[mf][nf], wh[mf], vl[nf]);
                    mma_bf16(oacc[mf][nf], wl[mf], vh[nf]);
                }
        }
        __syncthreads();
    }

    // ---- epilogue ----
    float* obuf  = reinterpret_cast<float*>(smem + A_STG);
    float* rsbuf = reinterpret_cast<float*>(smem + A_STG + 32768);

    #pragma unroll
    for (int mf = 0; mf < 2; mf++)
        #pragma unroll
        for (int hf = 0; hf < 2; hf++) {
            float v = rsum[mf][hf];
            v += __shfl_xor_sync(0xffffffffu, v, 1);
            v += __shfl_xor_sync(0xffffffffu, v, 2);
            rsum[mf][hf] = v;
        }

    const int g  = lane >> 2;
    const int tq = lane & 3;
    if (tq == 0) {
        #pragma unroll
        for (int mf = 0; mf < 2; mf++)
            #pragma unroll
            for (int hf = 0; hf < 2; hf++) {
                int row = wq * 32 + mf * 16 + hf * 8 + g;
                rsbuf[row * 2 + wn] = rsum[mf][hf];
            }
    }
    if (wn == 0) {
        #pragma unroll
        for (int mf = 0; mf < 2; mf++) {
            int r0 = wq * 32 + mf * 16 + g;
            #pragma unroll
            for (int nf = 0; nf < 8; nf++) {
                int col = nf * 8 + 2 * tq;
                *reinterpret_cast<float2*>(obuf + r0 * 64 + col) =
                    make_float2(oacc[mf][nf][0], oacc[mf][nf][1]);
                *reinterpret_cast<float2*>(obuf + (r0 + 8) * 64 + col) =
                    make_float2(oacc[mf][nf][2], oacc[mf][nf][3]);
            }
        }
    }
    __syncthreads();

    if (wn == 1) {
        #pragma unroll
        for (int mf = 0; mf < 2; mf++) {
            #pragma unroll
            for (int hf = 0; hf < 2; hf++) {
                int row = wq * 32 + mf * 16 + hf * 8 + g;
                float rtot = rsbuf[row * 2 + 0] + rsbuf[row * 2 + 1] + 1e-6f;
                float inv = 1.0f / rtot;
                size_t gbase = (size_t)(m0 + row) * DMODEL + cb;
                #pragma unroll
                for (int nf = 0; nf < 8; nf++) {
                    int col = nf * 8 + 2 * tq;
                    float o0 = (obuf[row * 64 + col]     + oacc[mf][nf][hf*2+0]) * inv;
                    float o1 = (obuf[row * 64 + col + 1] + oacc[mf][nf][hf*2+1]) * inv;
                    __nv_bfloat16 h0 = __float2bfloat16(o0);
                    __nv_bfloat16 h1 = __float2bfloat16(o1);
                    __nv_bfloat162 ph(h0, h1);
                    __nv_bfloat162 pl(__float2bfloat16(o0 - __bfloat162float(h0)),
                                      __float2bfloat16(o1 - __bfloat162float(h1)));
                    *reinterpret_cast<__nv_bfloat162*>(g_oh + gbase + col) = ph;
                    *reinterpret_cast<__nv_bfloat162*>(g_ol + gbase + col) = pl;
                }
            }
        }
    }
}

// ---------------------------------------------------------------------------
extern "C" void kernel_launch(void* const* d_in, const int* in_sizes, int n_in,
                              void* d_out, int out_size)
{
    (void)in_sizes; (void)n_in; (void)out_size;
    const float* x  = (const float*)d_in[0];
    const float* Wq = (const float*)d_in[1];
    const float* Wk = (const float*)d_in[2];
    const float* Wv = (const float*)d_in[3];
    const float* Wo = (const float*)d_in[4];
    const float* bo = (const float*)d_in[5];
    float* out = (float*)d_out;

    __nv_bfloat16 *xh, *xl, *oh, *ol;
    __nv_bfloat16 *wqh, *wql, *wkh, *wkl, *wvh, *wvl, *woh, *wol;
    cudaGetSymbolAddress((void**)&xh,  g_xh);
    cudaGetSymbolAddress((void**)&xl,  g_xl);
    cudaGetSymbolAddress((void**)&oh,  g_oh);
    cudaGetSymbolAddress((void**)&ol,  g_ol);
    cudaGetSymbolAddress((void**)&wqh, g_Wqh);
    cudaGetSymbolAddress((void**)&wql, g_Wql);
    cudaGetSymbolAddress((void**)&wkh, g_Wkh);
    cudaGetSymbolAddress((void**)&wkl, g_Wkl);
    cudaGetSymbolAddress((void**)&wvh, g_Wvh);
    cudaGetSymbolAddress((void**)&wvl, g_Wvl);
    cudaGetSymbolAddress((void**)&woh, g_Woh);
    cudaGetSymbolAddress((void**)&wol, g_Wol);

    cudaFuncSetAttribute(gemm_qkv_kernel, cudaFuncAttributeMaxDynamicSharedMemorySize, G_SMEM_BYTES);
    cudaFuncSetAttribute(gemm_tc, cudaFuncAttributeMaxDynamicSharedMemorySize, G_SMEM_BYTES);
    cudaFuncSetAttribute(attn_mma_kernel, cudaFuncAttributeMaxDynamicSharedMemorySize, A_SMEM);

    const int XN4 = MROWS*DMODEL/4;
    const int WN4 = DMODEL*DMODEL/4;
    split_kernel<<<XN4/256, 256>>>(x,  xh, xl, XN4);
    split_kernel<<<WN4/256, 256>>>(Wq, wqh, wql, WN4);
    split_kernel<<<WN4/256, 256>>>(Wk, wkh, wkl, WN4);
    split_kernel<<<WN4/256, 256>>>(Wv, wvh, wvl, WN4);
    split_kernel<<<WN4/256, 256>>>(Wo, woh, wol, WN4);

    gemm_qkv_kernel<<<dim3(DMODEL/128, MROWS/128, 3), 256, G_SMEM_BYTES>>>();

    l2norm_split_kernel<<<16384, 256>>>();
    vtrans_split_kernel<<<dim3(MROWS/32, DMODEL/32), dim3(32, 8)>>>();

    attn_mma_kernel<<<dim3(16, BATCH * NHEADS), 256, A_SMEM>>>();

    gemm_tc<<<dim3(DMODEL/128, MROWS/128), 256, G_SMEM_BYTES>>>(
        oh, ol, woh, wol, bo, out, DMODEL, DMODEL);
}

// round 8
// speedup vs baseline: 1.0035x; 1.0035x over previous
#include <cuda_runtime.h>
#include <cuda_bf16.h>
#include <math.h>
#include <stdint.h>

#define NHEADS  16
#define HDIM    64
#define BATCH   2
#define SEQ     2048
#define DMODEL  1024
#define MROWS   (BATCH*SEQ)   // 4096

// ---------------------------------------------------------------------------
// Scratch (device globals — no allocation allowed)
// ---------------------------------------------------------------------------
__device__ float g_Q[MROWS*DMODEL];
__device__ float g_K[MROWS*DMODEL];
__device__ float g_V[MROWS*DMODEL];

__device__ __nv_bfloat16 g_xh[MROWS*DMODEL];
__device__ __nv_bfloat16 g_xl[MROWS*DMODEL];
__device__ __nv_bfloat16 g_oh[MROWS*DMODEL];
__device__ __nv_bfloat16 g_ol[MROWS*DMODEL];
__device__ __nv_bfloat16 g_Wqh[DMODEL*DMODEL];
__device__ __nv_bfloat16 g_Wql[DMODEL*DMODEL];
__device__ __nv_bfloat16 g_Wkh[DMODEL*DMODEL];
__device__ __nv_bfloat16 g_Wkl[DMODEL*DMODEL];
__device__ __nv_bfloat16 g_Wvh[DMODEL*DMODEL];
__device__ __nv_bfloat16 g_Wvl[DMODEL*DMODEL];
__device__ __nv_bfloat16 g_Woh[DMODEL*DMODEL];
__device__ __nv_bfloat16 g_Wol[DMODEL*DMODEL];

// attention operands (bf16 hi/lo)
__device__ __nv_bfloat16 g_Qh[MROWS*DMODEL];
__device__ __nv_bfloat16 g_Ql[MROWS*DMODEL];
__device__ __nv_bfloat16 g_Kh[MROWS*DMODEL];
__device__ __nv_bfloat16 g_Kl[MROWS*DMODEL];
__device__ __nv_bfloat16 g_Vth[DMODEL*MROWS];   // V^T: [1024][4096]
__device__ __nv_bfloat16 g_Vtl[DMODEL*MROWS];

// ---------------------------------------------------------------------------
// PTX helpers (sm_80-class only — tcgen05 NOT available on this target)
// ---------------------------------------------------------------------------
__device__ __forceinline__ uint32_t smem_u32(const void* p) {
    uint32_t a;
    asm("{ .reg .u64 t; cvta.to.shared.u64 t, %1; cvt.u32.u64 %0, t; }"
        : "=r"(a) : "l"(p));
    return a;
}

__device__ __forceinline__ void cp_async16(uint32_t dst, const void* src) {
    asm volatile("cp.async.cg.shared.global [%0], [%1], 16;" :: "r"(dst), "l"(src));
}
__device__ __forceinline__ void cp_commit() { asm volatile("cp.async.commit_group;"); }

__device__ __forceinline__ void ldm_x4(uint32_t addr, uint32_t& r0, uint32_t& r1,
                                       uint32_t& r2, uint32_t& r3) {
    asm volatile("ldmatrix.sync.aligned.m8n8.x4.shared.b16 {%0,%1,%2,%3}, [%4];"
                 : "=r"(r0), "=r"(r1), "=r"(r2), "=r"(r3) : "r"(addr));
}
__device__ __forceinline__ void ldm_x2(uint32_t addr, uint32_t& r0, uint32_t& r1) {
    asm volatile("ldmatrix.sync.aligned.m8n8.x2.shared.b16 {%0,%1}, [%2];"
                 : "=r"(r0), "=r"(r1) : "r"(addr));
}

__device__ __forceinline__ void mma_bf16(float* d, const uint32_t* a, const uint32_t* b) {
    asm volatile(
        "mma.sync.aligned.m16n8k16.row.col.f32.bf16.bf16.f32 "
        "{%0,%1,%2,%3}, {%4,%5,%6,%7}, {%8,%9}, {%0,%1,%2,%3};"
        : "+f"(d[0]), "+f"(d[1]), "+f"(d[2]), "+f"(d[3])
        : "r"(a[0]), "r"(a[1]), "r"(a[2]), "r"(a[3]), "r"(b[0]), "r"(b[1]));
}

// 128B-row swizzle (8 chunks of 16B), chunk ^= row&7
__device__ __forceinline__ uint32_t sw_off(int row, int chunk) {
    return (uint32_t)(row * 128 + ((chunk ^ (row & 7)) << 4));
}
// 256B-row swizzle (16 chunks of 16B), low-3 bits of chunk ^= row&7
__device__ __forceinline__ uint32_t swv_off(int row, int chunk) {
    return (uint32_t)(row * 256 + ((chunk ^ (row & 7)) << 4));
}

// fast angular weight: w = max(1 - acos(clip(c))/pi, eps)^16
// acos via A&S 4.4.46: acos(t) = sqrt(1-t)*P7(t), |err| ~ 2e-8 rad
__device__ __forceinline__ float ang_w(float x) {
    float c = fminf(fmaxf(x, -0.999f), 0.999f);
    float t = fabsf(c);
    float p = -0.0012624911f;
    p = fmaf(p, t,  0.0066700901f);
    p = fmaf(p, t, -0.0170881256f);
    p = fmaf(p, t,  0.0308918810f);
    p = fmaf(p, t, -0.0501743046f);
    p = fmaf(p, t,  0.0889789874f);
    p = fmaf(p, t, -0.2145988016f);
    p = fmaf(p, t,  1.5707963050f);
    float u = 1.0f - t;                 // >= 0.001
    float r = u * __frsqrt_rn(u) * p * 0.31830988618379067f;   // acos(|c|)/pi
    float s = (c >= 0.0f) ? (1.0f - r) : r;
    s = fmaxf(s, 1e-6f);
    float s2 = s*s, s4 = s2*s2, s8 = s4*s4;
    return s8 * s8;
}

// ---------------------------------------------------------------------------
// Split fp32 -> bf16 hi + bf16 lo (residual)
// ---------------------------------------------------------------------------
__global__ void split_kernel(const float* __restrict__ s,
                             __nv_bfloat16* __restrict__ h,
                             __nv_bfloat16* __restrict__ l, int n4)
{
    int i = blockIdx.x * blockDim.x + threadIdx.x;
    if (i >= n4) return;
    float4 v = reinterpret_cast<const float4*>(s)[i];
    __nv_bfloat16 h0 = __float2bfloat16(v.x);
    __nv_bfloat16 h1 = __float2bfloat16(v.y);
    __nv_bfloat16 h2 = __float2bfloat16(v.z);
    __nv_bfloat16 h3 = __float2bfloat16(v.w);
    __nv_bfloat16 l0 = __float2bfloat16(v.x - __bfloat162float(h0));
    __nv_bfloat16 l1 = __float2bfloat16(v.y - __bfloat162float(h1));
    __nv_bfloat16 l2 = __float2bfloat16(v.z - __bfloat162float(h2));
    __nv_bfloat16 l3 = __float2bfloat16(v.w - __bfloat162float(h3));
    __nv_bfloat162* hp = reinterpret_cast<__nv_bfloat162*>(h);
    __nv_bfloat162* lp = reinterpret_cast<__nv_bfloat162*>(l);
    hp[2*i]   = __nv_bfloat162(h0, h1);
    hp[2*i+1] = __nv_bfloat162(h2, h3);
    lp[2*i]   = __nv_bfloat162(l0, l1);
    lp[2*i+1] = __nv_bfloat162(l2, l3);
}

// ---------------------------------------------------------------------------
// mma.sync bf16 GEMM core (NT): C = A*B^T (+bias), hi/lo split.
// Tile 128x128, KC=64, 2-stage double buffer (R4-proven issue order),
// 256 threads, 8 warps (2Mx4N).
// ---------------------------------------------------------------------------
#define G_SUB      16384
#define G_STAGE_B  (4*G_SUB)
#define G_SMEM_BYTES (2*G_STAGE_B)   // 131072

__device__ __forceinline__ void gemm_core(
    const __nv_bfloat16* __restrict__ Ah, const __nv_bfloat16* __restrict__ Al,
    const __nv_bfloat16* __restrict__ Bh, const __nv_bfloat16* __restrict__ Bl,
    const float* __restrict__ bias, float* __restrict__ C,
    int N, int K, uint32_t sb)
{
    const int tid  = threadIdx.x;
    const int wid  = tid >> 5, lane = tid & 31;
    const int wm   = wid & 1;
    const int wn   = wid >> 1;
    const int bn = blockIdx.x * 128, bm = blockIdx.y * 128;

    const __nv_bfloat16* gsrc[4] = {Ah, Al, Bh, Bl};
    const int rbase[4] = {bm, bm, bn, bn};

    float acc[4][4][4];
    #pragma unroll
    for (int i = 0; i < 4; i++)
        #pragma unroll
        for (int j = 0; j < 4; j++)
            #pragma unroll
            for (int r = 0; r < 4; r++) acc[i][j][r] = 0.0f;

    const int nk = K / 64;

    auto load_stage = [&](int c) {
        uint32_t st = sb + (uint32_t)(c & 1) * G_STAGE_B;
        size_t koff = (size_t)c * 64;
        #pragma unroll
        for (int t = 0; t < 4; t++) {
            const __nv_bfloat16* g = gsrc[t];
            #pragma unroll
            for (int u = 0; u < 4; u++) {
                int idx = tid + u * 256;
                int r = idx >> 3, ch = idx & 7;
                const void* src = g + (size_t)(rbase[t] + r) * K + koff + ch * 8;
                cp_async16(st + t * G_SUB + sw_off(r, ch), src);
            }
        }
    };

    load_stage(0);
    cp_commit();

    for (int c = 0; c < nk; c++) {
        if (c + 1 < nk) { load_stage(c + 1); cp_commit(); }
        if (c + 1 < nk) asm volatile("cp.async.wait_group 1;" ::: "memory");
        else            asm volatile("cp.async.wait_group 0;" ::: "memory");
        __syncthreads();

        uint32_t st  = sb + (uint32_t)(c & 1) * G_STAGE_B;
        uint32_t ahB = st, alB = st + G_SUB, bhB = st + 2*G_SUB, blB = st + 3*G_SUB;

        #pragma unroll
        for (int ks = 0; ks < 4; ks++) {
            uint32_t bh[4][2], bl[4][2];
            {
                int r  = wn * 32 + (lane & 7);
                int chv = ks * 2 + ((lane >> 3) & 1);
                #pragma unroll
                for (int nf = 0; nf < 4; nf++) {
                    int row = r + nf * 8;
                    uint32_t off = sw_off(row, chv);
                    ldm_x2(bhB + off, bh[nf][0], bh[nf][1]);
                    ldm_x2(blB + off, bl[nf][0], bl[nf][1]);
                }
            }
            #pragma unroll
            for (int mf = 0; mf < 4; mf++) {
                int row = wm * 64 + mf * 16 + (lane & 15);
                int chv = ks * 2 + (lane >> 4);
                uint32_t off = sw_off(row, chv);
                uint32_t ah[4], al[4];
                ldm_x4(ahB + off, ah[0], ah[1], ah[2], ah[3]);
                ldm_x4(alB + off, al[0], al[1], al[2], al[3]);
                #pragma unroll
                for (int nf = 0; nf < 4; nf++) {
                    mma_bf16(acc[mf][nf], ah, bh[nf]);
                    mma_bf16(acc[mf][nf], ah, bl[nf]);
                    mma_bf16(acc[mf][nf], al, bh[nf]);
                }
            }
        }
        __syncthreads();
    }

    const int g  = lane >> 2;
    const int tq = lane & 3;
    #pragma unroll
    for (int mf = 0; mf < 4; mf++) {
        int row0 = bm + wm * 64 + mf * 16 + g;
        #pragma unroll
        for (int nf = 0; nf < 4; nf++) {
            int col = bn + wn * 32 + nf * 8 + 2 * tq;
            float b0 = 0.f, b1 = 0.f;
            if (bias) { b0 = bias[col]; b1 = bias[col + 1]; }
            float2 v0, v1;
            v0.x = acc[mf][nf][0] + b0; v0.y = acc[mf][nf][1] + b1;
            v1.x = acc[mf][nf][2] + b0; v1.y = acc[mf][nf][3] + b1;
            *reinterpret_cast<float2*>(C + (size_t)row0 * N + col)       = v0;
            *reinterpret_cast<float2*>(C + (size_t)(row0 + 8) * N + col) = v1;
        }
    }
}

// merged QKV projection: grid.z selects weight/output
__global__ __launch_bounds__(256) void gemm_qkv_kernel()
{
    extern __shared__ __align__(128) char smem[];
    uint32_t sb = smem_u32(smem);
    const __nv_bfloat16* Bh;
    const __nv_bfloat16* Bl;
    float* C;
    switch (blockIdx.z) {
        case 0:  Bh = g_Wqh; Bl = g_Wql; C = g_Q; break;
        case 1:  Bh = g_Wkh; Bl = g_Wkl; C = g_K; break;
        default: Bh = g_Wvh; Bl = g_Wvl; C = g_V; break;
    }
    gemm_core(g_xh, g_xl, Bh, Bl, nullptr, C, DMODEL, DMODEL, sb);
}

// single GEMM (output projection, with bias)
__global__ __launch_bounds__(256) void gemm_tc(
    const __nv_bfloat16* __restrict__ Ah, const __nv_bfloat16* __restrict__ Al,
    const __nv_bfloat16* __restrict__ Bh, const __nv_bfloat16* __restrict__ Bl,
    const float* __restrict__ bias, float* __restrict__ C, int N, int K)
{
    extern __shared__ __align__(128) char smem[];
    uint32_t sb = smem_u32(smem);
    gemm_core(Ah, Al, Bh, Bl, bias, C, N, K, sb);
}

// ---------------------------------------------------------------------------
// L2-normalize each 64-float head chunk of g_Q / g_K, write bf16 hi/lo.
// ---------------------------------------------------------------------------
__global__ void l2norm_split_kernel()
{
    const int NC = MROWS * NHEADS;
    int gw   = (blockIdx.x * blockDim.x + threadIdx.x) >> 5;
    int lane = threadIdx.x & 31;
    const float* src;
    __nv_bfloat16 *dh, *dl;
    size_t off;
    if (gw < NC) { src = g_Q; dh = g_Qh; dl = g_Ql; off = (size_t)gw * HDIM; }
    else         { src = g_K; dh = g_Kh; dl = g_Kl; off = (size_t)(gw - NC) * HDIM; }
    float v0 = src[off + lane];
    float v1 = src[off + lane + 32];
    float ss = v0*v0 + v1*v1;
    #pragma unroll
    for (int o = 16; o > 0; o >>= 1) ss += __shfl_xor_sync(0xffffffffu, ss, o);
    float inv = 1.0f / fmaxf(sqrtf(ss), 1e-6f);
    float n0 = v0 * inv, n1 = v1 * inv;
    __nv_bfloat16 h0 = __float2bfloat16(n0);
    __nv_bfloat16 h1 = __float2bfloat16(n1);
    dh[off + lane]      = h0;
    dh[off + lane + 32] = h1;
    dl[off + lane]      = __float2bfloat16(n0 - __bfloat162float(h0));
    dl[off + lane + 32] = __float2bfloat16(n1 - __bfloat162float(h1));
}

// ---------------------------------------------------------------------------
// V transpose + split: g_V [4096][1024] fp32 -> g_Vth/g_Vtl [1024][4096] bf16
// ---------------------------------------------------------------------------
__global__ void vtrans_split_kernel()
{
    __shared__ float t[32][33];
    int s0 = blockIdx.x * 32, d0 = blockIdx.y * 32;
    int x = threadIdx.x, y = threadIdx.y;
    #pragma unroll
    for (int k = 0; k < 4; k++)
        t[y + k*8][x] = g_V[(size_t)(s0 + y + k*8) * DMODEL + d0 + x];
    __syncthreads();
    #pragma unroll
    for (int k = 0; k < 4; k++) {
        int d = d0 + y + k*8;
        float v = t[x][y + k*8];
        __nv_bfloat16 h = __float2bfloat16(v);
        g_Vth[(size_t)d * MROWS + s0 + x] = h;
        g_Vtl[(size_t)d * MROWS + s0 + x] = __float2bfloat16(v - __bfloat162float(h));
    }
}

// ---------------------------------------------------------------------------
// mma.sync angular attention (2-stage, R4-proven) + fast acos polynomial.
// grid (16 q-tiles, 32 bh), 256 threads, 8 warps = 4 (q) x 2 (k-half).
// ---------------------------------------------------------------------------
#define A_Q     0
#define A_STG   32768
#define A_STAGE 65536
#define A_SMEM  (A_STG + 2*A_STAGE)    // 163840

__global__ __launch_bounds__(256, 1) void attn_mma_kernel()
{
    extern __shared__ __align__(128) char smem[];
    uint32_t sb = smem_u32(smem);
    const int tid  = threadIdx.x;
    const int wid  = tid >> 5, lane = tid & 31;
    const int wq   = wid & 3;
    const int wn   = wid >> 2;
    const int qt   = blockIdx.x;
    const int b    = blockIdx.y / NHEADS;
    const int h    = blockIdx.y % NHEADS;
    const int m0   = b * SEQ + qt * 128;
    const int cb   = h * HDIM;

    #pragma unroll
    for (int u = 0; u < 4; u++) {
        int idx = tid + u * 256;
        int r = idx >> 3, ch = idx & 7;
        const __nv_bfloat16* s0 = g_Qh + (size_t)(m0 + r) * DMODEL + cb + ch * 8;
        const __nv_bfloat16* s1 = g_Ql + (size_t)(m0 + r) * DMODEL + cb + ch * 8;
        cp_async16(sb + A_Q + sw_off(r, ch), s0);
        cp_async16(sb + A_Q + 16384 + sw_off(r, ch), s1);
    }

    auto load_stage = [&](int kt) {
        uint32_t st = sb + A_STG + (uint32_t)(kt & 1) * A_STAGE;
        int k0 = b * SEQ + kt * 128;
        #pragma unroll
        for (int u = 0; u < 4; u++) {
            int idx = tid + u * 256;
            int r = idx >> 3, ch = idx & 7;
            cp_async16(st + sw_off(r, ch),
                       g_Kh + (size_t)(k0 + r) * DMODEL + cb + ch * 8);
            cp_async16(st + 16384 + sw_off(r, ch),
                       g_Kl + (size_t)(k0 + r) * DMODEL + cb + ch * 8);
        }
        #pragma unroll
        for (int u = 0; u < 4; u++) {
            int idx = tid + u * 256;
            int r = idx >> 4, ch = idx & 15;
            cp_async16(st + 32768 + swv_off(r, ch),
                       g_Vth + (size_t)(cb + r) * MROWS + k0 + ch * 8);
            cp_async16(st + 49152 + swv_off(r, ch),
                       g_Vtl + (size_t)(cb + r) * MROWS + k0 + ch * 8);
        }
    };

    load_stage(0);
    cp_commit();

    float oacc[2][8][4];
    #pragma unroll
    for (int mf = 0; mf < 2; mf++)
        #pragma unroll
        for (int nf = 0; nf < 8; nf++)
            #pragma unroll
            for (int r = 0; r < 4; r++) oacc[mf][nf][r] = 0.0f;
    float rsum[2][2] = {{0.f,0.f},{0.f,0.f}};

    for (int kt = 0; kt < 16; kt++) {
        if (kt + 1 < 16) { load_stage(kt + 1); cp_commit();
                           asm volatile("cp.async.wait_group 1;" ::: "memory"); }
        else             { asm volatile("cp.async.wait_group 0;" ::: "memory"); }
        __syncthreads();

        uint32_t st  = sb + A_STG + (uint32_t)(kt & 1) * A_STAGE;
        uint32_t khB = st, klB = st + 16384, vhB = st + 32768, vlB = st + 49152;

        float sacc[2][8][4];
        #pragma unroll
        for (int mf = 0; mf < 2; mf++)
            #pragma unroll
            for (int nf = 0; nf < 8; nf++)
                #pragma unroll
                for (int r = 0; r < 4; r++) sacc[mf][nf][r] = 0.0f;

        #pragma unroll
        for (int ks = 0; ks < 4; ks++) {
            uint32_t kh[8][2], kl[8][2];
            {
                int r  = wn * 64 + (lane & 7);
                int chv = ks * 2 + ((lane >> 3) & 1);
                #pragma unroll
                for (int nf = 0; nf < 8; nf++) {
                    uint32_t off = sw_off(r + nf * 8, chv);
                    ldm_x2(khB + off, kh[nf][0], kh[nf][1]);
                    ldm_x2(klB + off, kl[nf][0], kl[nf][1]);
                }
            }
            #pragma unroll
            for (int mf = 0; mf < 2; mf++) {
                int row = wq * 32 + mf * 16 + (lane & 15);
                int chv = ks * 2 + (lane >> 4);
                uint32_t off = sw_off(row, chv);
                uint32_t qh[4], ql[4];
                ldm_x4(sb + A_Q + off, qh[0], qh[1], qh[2], qh[3]);
                ldm_x4(sb + A_Q + 16384 + off, ql[0], ql[1], ql[2], ql[3]);
                #pragma unroll
                for (int nf = 0; nf < 8; nf++) {
                    mma_bf16(sacc[mf][nf], qh, kh[nf]);
                    mma_bf16(sacc[mf][nf], qh, kl[nf]);
                    mma_bf16(sacc[mf][nf], ql, kh[nf]);
                }
            }
        }

        #pragma unroll
        for (int j = 0; j < 4; j++) {
            uint32_t wh[2][4], wl[2][4];
            #pragma unroll
            for (int mf = 0; mf < 2; mf++) {
                #pragma unroll
                for (int half = 0; half < 2; half++) {
                    int nf = 2*j + half;
                    float w[4];
                    #pragma unroll
                    for (int e = 0; e < 4; e++) w[e] = ang_w(sacc[mf][nf][e]);
                    rsum[mf][0] += w[0] + w[1];
                    rsum[mf][1] += w[2] + w[3];
                    __nv_bfloat162 ph0 = __floats2bfloat162_rn(w[0], w[1]);
                    __nv_bfloat162 ph1 = __floats2bfloat162_rn(w[2], w[3]);
                    float r0 = w[0] - __bfloat162float(ph0.x);
                    float r1 = w[1] - __bfloat162float(ph0.y);
                    float r2 = w[2] - __bfloat162float(ph1.x);
                    float r3 = w[3] - __bfloat162float(ph1.y);
                    __nv_bfloat162 pl0 = __floats2bfloat162_rn(r0, r1);
                    __nv_bfloat162 pl1 = __floats2bfloat162_rn(r2, r3);
                    wh[mf][0 + half*2] = *reinterpret_cast<uint32_t*>(&ph0);
                    wh[mf][1 + half*2] = *reinterpret_cast<uint32_t*>(&ph1);
                    wl[mf][0 + half*2] = *reinterpret_cast<uint32_t*>(&pl0);
                    wl[mf][1 + half*2] = *reinterpret_cast<uint32_t*>(&pl1);
                }
            }
            uint32_t vh[8][2], vl[8][2];
            {
                int r   = lane & 7;
                int chv = wn * 8 + j * 2 + ((lane >> 3) & 1);
                #pragma unroll
                for (int nf = 0; nf < 8; nf++) {
                    uint32_t off = swv_off(r + nf * 8, chv);
                    ldm_x2(vhB + off, vh[nf][0], vh[nf][1]);
                    ldm_x2(vlB + off, vl[nf][0], vl[nf][1]);
                }
            }
            #pragma unroll
            for (int mf = 0; mf < 2; mf++)
                #pragma unroll
                for (int nf = 0; nf < 8; nf++) {
                    mma_bf16(oacc[mf][nf], wh[mf], vh[nf]);
                    mma_bf16(oacc[mf][nf], wh[mf], vl[nf]);
                    mma_bf16(oacc[mf][nf], wl[mf], vh[nf]);
                }
        }
        __syncthreads();
    }

    // ---- epilogue ----
    float* obuf  = reinterpret_cast<float*>(smem + A_STG);
    float* rsbuf = reinterpret_cast<float*>(smem + A_STG + 32768);

    #pragma unroll
    for (int mf = 0; mf < 2; mf++)
        #pragma unroll
        for (int hf = 0; hf < 2; hf++) {
            float v = rsum[mf][hf];
            v += __shfl_xor_sync(0xffffffffu, v, 1);
            v += __shfl_xor_sync(0xffffffffu, v, 2);
            rsum[mf][hf] = v;
        }

    const int g  = lane >> 2;
    const int tq = lane & 3;
    if (tq == 0) {
        #pragma unroll
        for (int mf = 0; mf < 2; mf++)
            #pragma unroll
            for (int hf = 0; hf < 2; hf++) {
                int row = wq * 32 + mf * 16 + hf * 8 + g;
                rsbuf[row * 2 + wn] = rsum[mf][hf];
            }
    }
    if (wn == 0) {
        #pragma unroll
        for (int mf = 0; mf < 2; mf++) {
            int r0 = wq * 32 + mf * 16 + g;
            #pragma unroll
            for (int nf = 0; nf < 8; nf++) {
                int col = nf * 8 + 2 * tq;
                *reinterpret_cast<float2*>(obuf + r0 * 64 + col) =
                    make_float2(oacc[mf][nf][0], oacc[mf][nf][1]);
                *reinterpret_cast<float2*>(obuf + (r0 + 8) * 64 + col) =
                    make_float2(oacc[mf][nf][2], oacc[mf][nf][3]);
            }
        }
    }
    __syncthreads();

    if (wn == 1) {
        #pragma unroll
        for (int mf = 0; mf < 2; mf++) {
            #pragma unroll
            for (int hf = 0; hf < 2; hf++) {
                int row = wq * 32 + mf * 16 + hf * 8 + g;
                float rtot = rsbuf[row * 2 + 0] + rsbuf[row * 2 + 1] + 1e-6f;
                float inv = 1.0f / rtot;
                size_t gbase = (size_t)(m0 + row) * DMODEL + cb;
                #pragma unroll
                for (int nf = 0; nf < 8; nf++) {
                    int col = nf * 8 + 2 * tq;
                    float o0 = (obuf[row * 64 + col]     + oacc[mf][nf][hf*2+0]) * inv;
                    float o1 = (obuf[row * 64 + col + 1] + oacc[mf][nf][hf*2+1]) * inv;
                    __nv_bfloat16 h0 = __float2bfloat16(o0);
                    __nv_bfloat16 h1 = __float2bfloat16(o1);
                    __nv_bfloat162 ph(h0, h1);
                    __nv_bfloat162 pl(__float2bfloat16(o0 - __bfloat162float(h0)),
                                      __float2bfloat16(o1 - __bfloat162float(h1)));
                    *reinterpret_cast<__nv_bfloat162*>(g_oh + gbase + col) = ph;
                    *reinterpret_cast<__nv_bfloat162*>(g_ol + gbase + col) = pl;
                }
            }
        }
    }
}

// ---------------------------------------------------------------------------
extern "C" void kernel_launch(void* const* d_in, const int* in_sizes, int n_in,
                              void* d_out, int out_size)
{
    (void)in_sizes; (void)n_in; (void)out_size;
    const float* x  = (const float*)d_in[0];
    const float* Wq = (const float*)d_in[1];
    const float* Wk = (const float*)d_in[2];
    const float* Wv = (const float*)d_in[3];
    const float* Wo = (const float*)d_in[4];
    const float* bo = (const float*)d_in[5];
    float* out = (float*)d_out;

    __nv_bfloat16 *xh, *xl, *oh, *ol;
    __nv_bfloat16 *wqh, *wql, *wkh, *wkl, *wvh, *wvl, *woh, *wol;
    cudaGetSymbolAddress((void**)&xh,  g_xh);
    cudaGetSymbolAddress((void**)&xl,  g_xl);
    cudaGetSymbolAddress((void**)&oh,  g_oh);
    cudaGetSymbolAddress((void**)&ol,  g_ol);
    cudaGetSymbolAddress((void**)&wqh, g_Wqh);
    cudaGetSymbolAddress((void**)&wql, g_Wql);
    cudaGetSymbolAddress((void**)&wkh, g_Wkh);
    cudaGetSymbolAddress((void**)&wkl, g_Wkl);
    cudaGetSymbolAddress((void**)&wvh, g_Wvh);
    cudaGetSymbolAddress((void**)&wvl, g_Wvl);
    cudaGetSymbolAddress((void**)&woh, g_Woh);
    cudaGetSymbolAddress((void**)&wol, g_Wol);

    cudaFuncSetAttribute(gemm_qkv_kernel, cudaFuncAttributeMaxDynamicSharedMemorySize, G_SMEM_BYTES);
    cudaFuncSetAttribute(gemm_tc, cudaFuncAttributeMaxDynamicSharedMemorySize, G_SMEM_BYTES);
    cudaFuncSetAttribute(attn_mma_kernel, cudaFuncAttributeMaxDynamicSharedMemorySize, A_SMEM);

    const int XN4 = MROWS*DMODEL/4;
    const int WN4 = DMODEL*DMODEL/4;
    split_kernel<<<XN4/256, 256>>>(x,  xh, xl, XN4);
    split_kernel<<<WN4/256, 256>>>(Wq, wqh, wql, WN4);
    split_kernel<<<WN4/256, 256>>>(Wk, wkh, wkl, WN4);
    split_kernel<<<WN4/256, 256>>>(Wv, wvh, wvl, WN4);
    split_kernel<<<WN4/256, 256>>>(Wo, woh, wol, WN4);

    gemm_qkv_kernel<<<dim3(DMODEL/128, MROWS/128, 3), 256, G_SMEM_BYTES>>>();

    l2norm_split_kernel<<<16384, 256>>>();
    vtrans_split_kernel<<<dim3(MROWS/32, DMODEL/32), dim3(32, 8)>>>();

    attn_mma_kernel<<<dim3(16, BATCH * NHEADS), 256, A_SMEM>>>();

    gemm_tc<<<dim3(DMODEL/128, MROWS/128), 256, G_SMEM_BYTES>>>(
        oh, ol, woh, wol, bo, out, DMODEL, DMODEL);
}

// round 13
// speedup vs baseline: 1.2892x; 1.2847x over previous
#include <cuda_runtime.h>
#include <cuda_bf16.h>
#include <math.h>
#include <stdint.h>

#define NHEADS  16
#define HDIM    64
#define BATCH   2
#define SEQ     2048
#define DMODEL  1024
#define MROWS   (BATCH*SEQ)   // 4096

// ---------------------------------------------------------------------------
// Scratch (device globals — no allocation allowed)
// ---------------------------------------------------------------------------
__device__ float g_Q[MROWS*DMODEL];
__device__ float g_K[MROWS*DMODEL];
__device__ float g_V[MROWS*DMODEL];

__device__ __nv_bfloat16 g_xh[MROWS*DMODEL];
__device__ __nv_bfloat16 g_xl[MROWS*DMODEL];
__device__ __nv_bfloat16 g_oh[MROWS*DMODEL];
__device__ __nv_bfloat16 g_ol[MROWS*DMODEL];
__device__ __nv_bfloat16 g_Wqh[DMODEL*DMODEL];
__device__ __nv_bfloat16 g_Wql[DMODEL*DMODEL];
__device__ __nv_bfloat16 g_Wkh[DMODEL*DMODEL];
__device__ __nv_bfloat16 g_Wkl[DMODEL*DMODEL];
__device__ __nv_bfloat16 g_Wvh[DMODEL*DMODEL];
__device__ __nv_bfloat16 g_Wvl[DMODEL*DMODEL];
__device__ __nv_bfloat16 g_Woh[DMODEL*DMODEL];
__device__ __nv_bfloat16 g_Wol[DMODEL*DMODEL];

// attention operands (bf16 hi/lo)
__device__ __nv_bfloat16 g_Qh[MROWS*DMODEL];
__device__ __nv_bfloat16 g_Ql[MROWS*DMODEL];
__device__ __nv_bfloat16 g_Kh[MROWS*DMODEL];
__device__ __nv_bfloat16 g_Kl[MROWS*DMODEL];
__device__ __nv_bfloat16 g_Vth[DMODEL*MROWS];   // V^T: [1024][4096]
__device__ __nv_bfloat16 g_Vtl[DMODEL*MROWS];

// ---------------------------------------------------------------------------
// PTX helpers (sm_80-class only — tcgen05 NOT available on this target)
// ---------------------------------------------------------------------------
__device__ __forceinline__ uint32_t smem_u32(const void* p) {
    uint32_t a;
    asm("{ .reg .u64 t; cvta.to.shared.u64 t, %1; cvt.u32.u64 %0, t; }"
        : "=r"(a) : "l"(p));
    return a;
}

__device__ __forceinline__ void cp_async16(uint32_t dst, const void* src) {
    asm volatile("cp.async.cg.shared.global [%0], [%1], 16;" :: "r"(dst), "l"(src));
}
__device__ __forceinline__ void cp_commit() { asm volatile("cp.async.commit_group;"); }

__device__ __forceinline__ void ldm_x4(uint32_t addr, uint32_t& r0, uint32_t& r1,
                                       uint32_t& r2, uint32_t& r3) {
    asm volatile("ldmatrix.sync.aligned.m8n8.x4.shared.b16 {%0,%1,%2,%3}, [%4];"
                 : "=r"(r0), "=r"(r1), "=r"(r2), "=r"(r3) : "r"(addr));
}
__device__ __forceinline__ void ldm_x2(uint32_t addr, uint32_t& r0, uint32_t& r1) {
    asm volatile("ldmatrix.sync.aligned.m8n8.x2.shared.b16 {%0,%1}, [%2];"
                 : "=r"(r0), "=r"(r1) : "r"(addr));
}

__device__ __forceinline__ void mma_bf16(float* d, const uint32_t* a, const uint32_t* b) {
    asm volatile(
        "mma.sync.aligned.m16n8k16.row.col.f32.bf16.bf16.f32 "
        "{%0,%1,%2,%3}, {%4,%5,%6,%7}, {%8,%9}, {%0,%1,%2,%3};"
        : "+f"(d[0]), "+f"(d[1]), "+f"(d[2]), "+f"(d[3])
        : "r"(a[0]), "r"(a[1]), "r"(a[2]), "r"(a[3]), "r"(b[0]), "r"(b[1]));
}

// swizzled smem offset: row-major 128B rows of 8x16B chunks, chunk ^= row&7
__device__ __forceinline__ uint32_t sw_off(int row, int chunk) {
    return (uint32_t)(row * 128 + ((chunk ^ (row & 7)) << 4));
}
// 256B-row swizzle (16 chunks of 16B), low-3 bits of chunk ^= row&7
__device__ __forceinline__ uint32_t swv_off(int row, int chunk) {
    return (uint32_t)(row * 256 + ((chunk ^ (row & 7)) << 4));
}

// ---------------------------------------------------------------------------
// Split fp32 -> bf16 hi + bf16 lo (residual)
// ---------------------------------------------------------------------------
__global__ void split_kernel(const float* __restrict__ s,
                             __nv_bfloat16* __restrict__ h,
                             __nv_bfloat16* __restrict__ l, int n4)
{
    int i = blockIdx.x * blockDim.x + threadIdx.x;
    if (i >= n4) return;
    float4 v = reinterpret_cast<const float4*>(s)[i];
    __nv_bfloat16 h0 = __float2bfloat16(v.x);
    __nv_bfloat16 h1 = __float2bfloat16(v.y);
    __nv_bfloat16 h2 = __float2bfloat16(v.z);
    __nv_bfloat16 h3 = __float2bfloat16(v.w);
    __nv_bfloat16 l0 = __float2bfloat16(v.x - __bfloat162float(h0));
    __nv_bfloat16 l1 = __float2bfloat16(v.y - __bfloat162float(h1));
    __nv_bfloat16 l2 = __float2bfloat16(v.z - __bfloat162float(h2));
    __nv_bfloat16 l3 = __float2bfloat16(v.w - __bfloat162float(h3));
    __nv_bfloat162* hp = reinterpret_cast<__nv_bfloat162*>(h);
    __nv_bfloat162* lp = reinterpret_cast<__nv_bfloat162*>(l);
    hp[2*i]   = __nv_bfloat162(h0, h1);
    hp[2*i+1] = __nv_bfloat162(h2, h3);
    lp[2*i]   = __nv_bfloat162(l0, l1);
    lp[2*i+1] = __nv_bfloat162(l2, l3);
}

// ---------------------------------------------------------------------------
// mma.sync bf16 GEMM (NT): C[m,n] = sum_k A[m,k]*B[n,k] (+bias),
// fp32-accurate via hi/lo split: D = Ah*Bh + Ah*Bl + Al*Bh.
// Tile 128x128, KC=64, double-buffered cp.async, 256 threads, 8 warps (2Mx4N).
// ---------------------------------------------------------------------------
#define G_SUB      16384                // one 128x64 bf16 subtile
#define G_STAGE_B  (4*G_SUB)            // Ah, Al, Bh, Bl
#define G_SMEM_BYTES (2*G_STAGE_B)      // 131072

__global__ __launch_bounds__(256) void gemm_tc(
    const __nv_bfloat16* __restrict__ Ah, const __nv_bfloat16* __restrict__ Al,
    const __nv_bfloat16* __restrict__ Bh, const __nv_bfloat16* __restrict__ Bl,
    const float* __restrict__ bias, float* __restrict__ C,
    int M, int N, int K)
{
    extern __shared__ __align__(128) char smem[];
    uint32_t sb = smem_u32(smem);
    const int tid  = threadIdx.x;
    const int wid  = tid >> 5, lane = tid & 31;
    const int wm   = wid & 1;           // warp row  (2 x 64)
    const int wn   = wid >> 1;          // warp col  (4 x 32)
    const int bn = blockIdx.x * 128, bm = blockIdx.y * 128;

    const __nv_bfloat16* gsrc[4] = {Ah, Al, Bh, Bl};
    const int rbase[4] = {bm, bm, bn, bn};

    float acc[4][4][4];
    #pragma unroll
    for (int i = 0; i < 4; i++)
        #pragma unroll
        for (int j = 0; j < 4; j++)
            #pragma unroll
            for (int r = 0; r < 4; r++) acc[i][j][r] = 0.0f;

    const int nk = K / 64;              // 16 K-chunks

    auto load_stage = [&](int c) {
        uint32_t st = sb + (uint32_t)(c & 1) * G_STAGE_B;
        size_t koff = (size_t)c * 64;
        #pragma unroll
        for (int t = 0; t < 4; t++) {
            const __nv_bfloat16* g = gsrc[t];
            #pragma unroll
            for (int u = 0; u < 4; u++) {
                int idx = tid + u * 256;            // 0..1023 chunks
                int r = idx >> 3, ch = idx & 7;
                const void* src = g + (size_t)(rbase[t] + r) * K + koff + ch * 8;
                cp_async16(st + t * G_SUB + sw_off(r, ch), src);
            }
        }
    };

    load_stage(0);
    cp_commit();

    for (int c = 0; c < nk; c++) {
        if (c + 1 < nk) { load_stage(c + 1); cp_commit(); }
        if (c + 1 < nk) asm volatile("cp.async.wait_group 1;" ::: "memory");
        else            asm volatile("cp.async.wait_group 0;" ::: "memory");
        __syncthreads();

        uint32_t st  = sb + (uint32_t)(c & 1) * G_STAGE_B;
        uint32_t ahB = st, alB = st + G_SUB, bhB = st + 2*G_SUB, blB = st + 3*G_SUB;

        #pragma unroll
        for (int ks = 0; ks < 4; ks++) {
            // B fragments (resident): 4 n-frags x (hi, lo)
            uint32_t bh[4][2], bl[4][2];
            {
                int r  = wn * 32 + (lane & 7);      // base n-row for this lane
                int chv = ks * 2 + ((lane >> 3) & 1);
                #pragma unroll
                for (int nf = 0; nf < 4; nf++) {
                    int row = r + nf * 8;
                    uint32_t off = sw_off(row, chv);
                    ldm_x2(bhB + off, bh[nf][0], bh[nf][1]);
                    ldm_x2(blB + off, bl[nf][0], bl[nf][1]);
                }
            }
            #pragma unroll
            for (int mf = 0; mf < 4; mf++) {
                int row = wm * 64 + mf * 16 + (lane & 15);
                int chv = ks * 2 + (lane >> 4);
                uint32_t off = sw_off(row, chv);
                uint32_t ah[4], al[4];
                ldm_x4(ahB + off, ah[0], ah[1], ah[2], ah[3]);
                ldm_x4(alB + off, al[0], al[1], al[2], al[3]);
                #pragma unroll
                for (int nf = 0; nf < 4; nf++) {
                    mma_bf16(acc[mf][nf], ah, bh[nf]);
                    mma_bf16(acc[mf][nf], ah, bl[nf]);
                    mma_bf16(acc[mf][nf], al, bh[nf]);
                }
            }
        }
        __syncthreads();
    }

    // --- epilogue ---
    const int g  = lane >> 2;           // 0..7
    const int tq = lane & 3;            // 0..3
    #pragma unroll
    for (int mf = 0; mf < 4; mf++) {
        int row0 = bm + wm * 64 + mf * 16 + g;
        #pragma unroll
        for (int nf = 0; nf < 4; nf++) {
            int col = bn + wn * 32 + nf * 8 + 2 * tq;
            float b0 = 0.f, b1 = 0.f;
            if (bias) { b0 = bias[col]; b1 = bias[col + 1]; }
            float2 v0, v1;
            v0.x = acc[mf][nf][0] + b0; v0.y = acc[mf][nf][1] + b1;
            v1.x = acc[mf][nf][2] + b0; v1.y = acc[mf][nf][3] + b1;
            *reinterpret_cast<float2*>(C + (size_t)row0 * N + col)       = v0;
            *reinterpret_cast<float2*>(C + (size_t)(row0 + 8) * N + col) = v1;
        }
    }
}

// ---------------------------------------------------------------------------
// L2-normalize each 64-float head chunk of g_Q / g_K, write bf16 hi/lo.
// ---------------------------------------------------------------------------
__global__ void l2norm_split_kernel()
{
    const int NC = MROWS * NHEADS;
    int gw   = (blockIdx.x * blockDim.x + threadIdx.x) >> 5;
    int lane = threadIdx.x & 31;
    const float* src;
    __nv_bfloat16 *dh, *dl;
    size_t off;
    if (gw < NC) { src = g_Q; dh = g_Qh; dl = g_Ql; off = (size_t)gw * HDIM; }
    else         { src = g_K; dh = g_Kh; dl = g_Kl; off = (size_t)(gw - NC) * HDIM; }
    float v0 = src[off + lane];
    float v1 = src[off + lane + 32];
    float ss = v0*v0 + v1*v1;
    #pragma unroll
    for (int o = 16; o > 0; o >>= 1) ss += __shfl_xor_sync(0xffffffffu, ss, o);
    float inv = 1.0f / fmaxf(sqrtf(ss), 1e-6f);
    float n0 = v0 * inv, n1 = v1 * inv;
    __nv_bfloat16 h0 = __float2bfloat16(n0);
    __nv_bfloat16 h1 = __float2bfloat16(n1);
    dh[off + lane]      = h0;
    dh[off + lane + 32] = h1;
    dl[off + lane]      = __float2bfloat16(n0 - __bfloat162float(h0));
    dl[off + lane + 32] = __float2bfloat16(n1 - __bfloat162float(h1));
}

// ---------------------------------------------------------------------------
// V transpose + split: g_V [4096][1024] fp32 -> g_Vth/g_Vtl [1024][4096] bf16
// ---------------------------------------------------------------------------
__global__ void vtrans_split_kernel()
{
    __shared__ float t[32][33];
    int s0 = blockIdx.x * 32, d0 = blockIdx.y * 32;
    int x = threadIdx.x, y = threadIdx.y;
    #pragma unroll
    for (int k = 0; k < 4; k++)
        t[y + k*8][x] = g_V[(size_t)(s0 + y + k*8) * DMODEL + d0 + x];
    __syncthreads();
    #pragma unroll
    for (int k = 0; k < 4; k++) {
        int d = d0 + y + k*8;
        float v = t[x][y + k*8];
        __nv_bfloat16 h = __float2bfloat16(v);
        g_Vth[(size_t)d * MROWS + s0 + x] = h;
        g_Vtl[(size_t)d * MROWS + s0 + x] = __float2bfloat16(v - __bfloat162float(h));
    }
}

// ---------------------------------------------------------------------------
// mma.sync angular attention.
// grid (16 q-tiles, 32 bh), 256 threads, 8 warps = 4 (q, 32 rows) x 2 (k, 64 cols).
// Smem: Qh,Ql (2x16KB) + 2 stages of {Kh,Kl (16KB ea), Vth,Vtl (16KB ea)} = 160KB
// ---------------------------------------------------------------------------
#define A_Q     0
#define A_STG   32768
#define A_STAGE 65536
#define A_SMEM  (A_STG + 2*A_STAGE)    // 163840

__global__ __launch_bounds__(256, 1) void attn_mma_kernel()
{
    extern __shared__ __align__(128) char smem[];
    uint32_t sb = smem_u32(smem);
    const int tid  = threadIdx.x;
    const int wid  = tid >> 5, lane = tid & 31;
    const int wq   = wid & 3;           // q-row group: 32 rows
    const int wn   = wid >> 2;          // k-half: 64 cols
    const int qt   = blockIdx.x;
    const int b    = blockIdx.y / NHEADS;
    const int h    = blockIdx.y % NHEADS;
    const int m0   = b * SEQ + qt * 128;
    const int cb   = h * HDIM;

    // ---- load Q tile (hi+lo), once ----
    #pragma unroll
    for (int u = 0; u < 4; u++) {
        int idx = tid + u * 256;               // 0..1023
        int r = idx >> 3, ch = idx & 7;
        const __nv_bfloat16* s0 = g_Qh + (size_t)(m0 + r) * DMODEL + cb + ch * 8;
        const __nv_bfloat16* s1 = g_Ql + (size_t)(m0 + r) * DMODEL + cb + ch * 8;
        cp_async16(sb + A_Q + sw_off(r, ch), s0);
        cp_async16(sb + A_Q + 16384 + sw_off(r, ch), s1);
    }

    auto load_stage = [&](int kt) {
        uint32_t st = sb + A_STG + (uint32_t)(kt & 1) * A_STAGE;
        int k0 = b * SEQ + kt * 128;
        #pragma unroll
        for (int u = 0; u < 4; u++) {
            int idx = tid + u * 256;
            int r = idx >> 3, ch = idx & 7;
            cp_async16(st + sw_off(r, ch),
                       g_Kh + (size_t)(k0 + r) * DMODEL + cb + ch * 8);
            cp_async16(st + 16384 + sw_off(r, ch),
                       g_Kl + (size_t)(k0 + r) * DMODEL + cb + ch * 8);
        }
        #pragma unroll
        for (int u = 0; u < 4; u++) {
            int idx = tid + u * 256;
            int r = idx >> 4, ch = idx & 15;   // r: 0..63 (d), ch: 0..15
            cp_async16(st + 32768 + swv_off(r, ch),
                       g_Vth + (size_t)(cb + r) * MROWS + k0 + ch * 8);
            cp_async16(st + 49152 + swv_off(r, ch),
                       g_Vtl + (size_t)(cb + r) * MROWS + k0 + ch * 8);
        }
    };

    load_stage(0);
    cp_commit();   // group: Q + stage0

    float oacc[2][8][4];
    #pragma unroll
    for (int mf = 0; mf < 2; mf++)
        #pragma unroll
        for (int nf = 0; nf < 8; nf++)
            #pragma unroll
            for (int r = 0; r < 4; r++) oacc[mf][nf][r] = 0.0f;
    float rsum[2][2] = {{0.f,0.f},{0.f,0.f}};

    const float INV_PI = 0.31830988618379067f;

    for (int kt = 0; kt < 16; kt++) {
        if (kt + 1 < 16) { load_stage(kt + 1); cp_commit();
                           asm volatile("cp.async.wait_group 1;" ::: "memory"); }
        else             { asm volatile("cp.async.wait_group 0;" ::: "memory"); }
        __syncthreads();

        uint32_t st  = sb + A_STG + (uint32_t)(kt & 1) * A_STAGE;
        uint32_t khB = st, klB = st + 16384, vhB = st + 32768, vlB = st + 49152;

        // ---- S = Qn Kn^T (hi/lo, fp32 acc) ----
        float sacc[2][8][4];
        #pragma unroll
        for (int mf = 0; mf < 2; mf++)
            #pragma unroll
            for (int nf = 0; nf < 8; nf++)
                #pragma unroll
                for (int r = 0; r < 4; r++) sacc[mf][nf][r] = 0.0f;

        #pragma unroll
        for (int ks = 0; ks < 4; ks++) {
            uint32_t kh[8][2], kl[8][2];
            {
                int r  = wn * 64 + (lane & 7);
                int chv = ks * 2 + ((lane >> 3) & 1);
                #pragma unroll
                for (int nf = 0; nf < 8; nf++) {
                    uint32_t off = sw_off(r + nf * 8, chv);
                    ldm_x2(khB + off, kh[nf][0], kh[nf][1]);
                    ldm_x2(klB + off, kl[nf][0], kl[nf][1]);
                }
            }
            #pragma unroll
            for (int mf = 0; mf < 2; mf++) {
                int row = wq * 32 + mf * 16 + (lane & 15);
                int chv = ks * 2 + (lane >> 4);
                uint32_t off = sw_off(row, chv);
                uint32_t qh[4], ql[4];
                ldm_x4(sb + A_Q + off, qh[0], qh[1], qh[2], qh[3]);
                ldm_x4(sb + A_Q + 16384 + off, ql[0], ql[1], ql[2], ql[3]);
                #pragma unroll
                for (int nf = 0; nf < 8; nf++) {
                    mma_bf16(sacc[mf][nf], qh, kh[nf]);
                    mma_bf16(sacc[mf][nf], qh, kl[nf]);
                    mma_bf16(sacc[mf][nf], ql, kh[nf]);
                }
            }
        }

        // ---- transform + PV, per k16 chunk j ----
        #pragma unroll
        for (int j = 0; j < 4; j++) {
            uint32_t wh[2][4], wl[2][4];
            #pragma unroll
            for (int mf = 0; mf < 2; mf++) {
                #pragma unroll
                for (int half = 0; half < 2; half++) {
                    int nf = 2*j + half;
                    float w[4];
                    #pragma unroll
                    for (int e = 0; e < 4; e++) {
                        float c = fminf(fmaxf(sacc[mf][nf][e], -0.999f), 0.999f);
                        float s = 1.0f - acosf(c) * INV_PI;
                        s = fmaxf(s, 1e-6f);
                        float s2 = s*s, s4 = s2*s2, s8 = s4*s4;
                        w[e] = s8 * s8;
                    }
                    rsum[mf][0] += w[0] + w[1];
                    rsum[mf][1] += w[2] + w[3];
                    // hi/lo packs
                    __nv_bfloat162 ph0 = __floats2bfloat162_rn(w[0], w[1]);
                    __nv_bfloat162 ph1 = __floats2bfloat162_rn(w[2], w[3]);
                    float r0 = w[0] - __bfloat162float(ph0.x);
                    float r1 = w[1] - __bfloat162float(ph0.y);
                    float r2 = w[2] - __bfloat162float(ph1.x);
                    float r3 = w[3] - __bfloat162float(ph1.y);
                    __nv_bfloat162 pl0 = __floats2bfloat162_rn(r0, r1);
                    __nv_bfloat162 pl1 = __floats2bfloat162_rn(r2, r3);
                    wh[mf][0 + half*2] = *reinterpret_cast<uint32_t*>(&ph0);
                    wh[mf][1 + half*2] = *reinterpret_cast<uint32_t*>(&ph1);
                    wl[mf][0 + half*2] = *reinterpret_cast<uint32_t*>(&pl0);
                    wl[mf][1 + half*2] = *reinterpret_cast<uint32_t*>(&pl1);
                }
            }
            // V^T fragments for this k-chunk
            uint32_t vh[8][2], vl[8][2];
            {
                int r   = lane & 7;                          // d row within 8
                int chv = wn * 8 + j * 2 + ((lane >> 3) & 1);
                #pragma unroll
                for (int nf = 0; nf < 8; nf++) {
                    uint32_t off = swv_off(r + nf * 8, chv);
                    ldm_x2(vhB + off, vh[nf][0], vh[nf][1]);
                    ldm_x2(vlB + off, vl[nf][0], vl[nf][1]);
                }
            }
            #pragma unroll
            for (int mf = 0; mf < 2; mf++)
                #pragma unroll
                for (int nf = 0; nf < 8; nf++) {
                    mma_bf16(oacc[mf][nf], wh[mf], vh[nf]);
                    mma_bf16(oacc[mf][nf], wh[mf], vl[nf]);
                    mma_bf16(oacc[mf][nf], wl[mf], vh[nf]);
                }
        }
        __syncthreads();
    }

    // ---- epilogue: cross-warp reduce (wn pairs), normalize, split-store ----
    float* obuf  = reinterpret_cast<float*>(smem + A_STG);          // [128][64]
    float* rsbuf = reinterpret_cast<float*>(smem + A_STG + 32768);  // [128][2]

    // rsum: reduce over lane&3 (column quads)
    #pragma unroll
    for (int mf = 0; mf < 2; mf++)
        #pragma unroll
        for (int hf = 0; hf < 2; hf++) {
            float v = rsum[mf][hf];
            v += __shfl_xor_sync(0xffffffffu, v, 1);
            v += __shfl_xor_sync(0xffffffffu, v, 2);
            rsum[mf][hf] = v;
        }

    const int g  = lane >> 2;
    const int tq = lane & 3;
    if (tq == 0) {
        #pragma unroll
        for (int mf = 0; mf < 2; mf++)
            #pragma unroll
            for (int hf = 0; hf < 2; hf++) {
                int row = wq * 32 + mf * 16 + hf * 8 + g;
                rsbuf[row * 2 + wn] = rsum[mf][hf];
            }
    }
    if (wn == 0) {
        #pragma unroll
        for (int mf = 0; mf < 2; mf++) {
            int r0 = wq * 32 + mf * 16 + g;
            #pragma unroll
            for (int nf = 0; nf < 8; nf++) {
                int col = nf * 8 + 2 * tq;
                *reinterpret_cast<float2*>(obuf + r0 * 64 + col) =
                    make_float2(oacc[mf][nf][0], oacc[mf][nf][1]);
                *reinterpret_cast<float2*>(obuf + (r0 + 8) * 64 + col) =
                    make_float2(oacc[mf][nf][2], oacc[mf][nf][3]);
            }
        }
    }
    __syncthreads();

    if (wn == 1) {
        #pragma unroll
        for (int mf = 0; mf < 2; mf++) {
            #pragma unroll
            for (int hf = 0; hf < 2; hf++) {
                int row = wq * 32 + mf * 16 + hf * 8 + g;
                float rtot = rsbuf[row * 2 + 0] + rsbuf[row * 2 + 1] + 1e-6f;
                float inv = 1.0f / rtot;
                size_t gbase = (size_t)(m0 + row) * DMODEL + cb;
                #pragma unroll
                for (int nf = 0; nf < 8; nf++) {
                    int col = nf * 8 + 2 * tq;
                    float o0 = (obuf[row * 64 + col]     + oacc[mf][nf][hf*2+0]) * inv;
                    float o1 = (obuf[row * 64 + col + 1] + oacc[mf][nf][hf*2+1]) * inv;
                    __nv_bfloat16 h0 = __float2bfloat16(o0);
                    __nv_bfloat16 h1 = __float2bfloat16(o1);
                    __nv_bfloat162 ph(h0, h1);
                    __nv_bfloat162 pl(__float2bfloat16(o0 - __bfloat162float(h0)),
                                      __float2bfloat16(o1 - __bfloat162float(h1)));
                    *reinterpret_cast<__nv_bfloat162*>(g_oh + gbase + col) = ph;
                    *reinterpret_cast<__nv_bfloat162*>(g_ol + gbase + col) = pl;
                }
            }
        }
    }
}

// ---------------------------------------------------------------------------
extern "C" void kernel_launch(void* const* d_in, const int* in_sizes, int n_in,
                              void* d_out, int out_size)
{
    (void)in_sizes; (void)n_in; (void)out_size;
    const float* x  = (const float*)d_in[0];
    const float* Wq = (const float*)d_in[1];
    const float* Wk = (const float*)d_in[2];
    const float* Wv = (const float*)d_in[3];
    const float* Wo = (const float*)d_in[4];
    const float* bo = (const float*)d_in[5];
    float* out = (float*)d_out;

    float *q, *k, *v;
    cudaGetSymbolAddress((void**)&q,  g_Q);
    cudaGetSymbolAddress((void**)&k,  g_K);
    cudaGetSymbolAddress((void**)&v,  g_V);

    __nv_bfloat16 *xh, *xl, *oh, *ol;
    __nv_bfloat16 *wqh, *wql, *wkh, *wkl, *wvh, *wvl, *woh, *wol;
    cudaGetSymbolAddress((void**)&xh,  g_xh);
    cudaGetSymbolAddress((void**)&xl,  g_xl);
    cudaGetSymbolAddress((void**)&oh,  g_oh);
    cudaGetSymbolAddress((void**)&ol,  g_ol);
    cudaGetSymbolAddress((void**)&wqh, g_Wqh);
    cudaGetSymbolAddress((void**)&wql, g_Wql);
    cudaGetSymbolAddress((void**)&wkh, g_Wkh);
    cudaGetSymbolAddress((void**)&wkl, g_Wkl);
    cudaGetSymbolAddress((void**)&wvh, g_Wvh);
    cudaGetSymbolAddress((void**)&wvl, g_Wvl);
    cudaGetSymbolAddress((void**)&woh, g_Woh);
    cudaGetSymbolAddress((void**)&wol, g_Wol);

    cudaFuncSetAttribute(gemm_tc, cudaFuncAttributeMaxDynamicSharedMemorySize, G_SMEM_BYTES);
    cudaFuncSetAttribute(attn_mma_kernel, cudaFuncAttributeMaxDynamicSharedMemorySize, A_SMEM);

    const int XN4 = MROWS*DMODEL/4;
    const int WN4 = DMODEL*DMODEL/4;
    split_kernel<<<XN4/256, 256>>>(x,  xh, xl, XN4);
    split_kernel<<<WN4/256, 256>>>(Wq, wqh, wql, WN4);
    split_kernel<<<WN4/256, 256>>>(Wk, wkh, wkl, WN4);
    split_kernel<<<WN4/256, 256>>>(Wv, wvh, wvl, WN4);
    split_kernel<<<WN4/256, 256>>>(Wo, woh, wol, WN4);

    dim3 gG(DMODEL/128, MROWS/128);  // (8, 32)
    gemm_tc<<<gG, 256, G_SMEM_BYTES>>>(xh, xl, wqh, wql, nullptr, q, MROWS, DMODEL, DMODEL);
    gemm_tc<<<gG, 256, G_SMEM_BYTES>>>(xh, xl, wkh, wkl, nullptr, k, MROWS, DMODEL, DMODEL);
    gemm_tc<<<gG, 256, G_SMEM_BYTES>>>(xh, xl, wvh, wvl, nullptr, v, MROWS, DMODEL, DMODEL);

    // 2 tensors * 65536 chunks, 1 warp each
    l2norm_split_kernel<<<16384, 256>>>();
    vtrans_split_kernel<<<dim3(MROWS/32, DMODEL/32), dim3(32, 8)>>>();

    attn_mma_kernel<<<dim3(16, BATCH * NHEADS), 256, A_SMEM>>>();

    gemm_tc<<<gG, 256, G_SMEM_BYTES>>>(oh, ol, woh, wol, bo, out, MROWS, DMODEL, DMODEL);
}